// round 9
// baseline (speedup 1.0000x reference)
#include <cuda_runtime.h>
#include <cuda_bf16.h>

// LIF recurrence over T=4 steps.
// x: [T=4, B=64, C=128, H=32, W=32] fp32; mem0: [1, C, H, W] fp32 (B-broadcast)
// out: [T, B, C, H, W] fp32 in {0,1}
// Per element: mem = tau*mem + x[t]; s = (mem > v_th); mem = s ? 0 : mem.
//
// HBM-bound. Replay-aware L2 policy with 256-bit accesses (sm_103 requires
// .v4.b64/.v8.b32 for L2 eviction-priority hints):
//   loads : ld.global.nc.L2::evict_first.v4.b64 (x streams, no L2 stickiness)
//   stores: st.global.L2::evict_last.v4.b64     (output sticks in 126MB L2;
//           subsequent graph replays overwrite in-L2, cutting DRAM writes)
// 1 x 32B chunk/thread/timestep, 256-thread blocks.

#define TAU 0.25f
#define V_TH 1.0f

struct F8 { float v[8]; };

__device__ __forceinline__ F8 ldg_stream8(const float* p) {
    unsigned long long r0, r1, r2, r3;
    asm volatile("ld.global.nc.L2::evict_first.v4.b64 {%0,%1,%2,%3}, [%4];"
                 : "=l"(r0), "=l"(r1), "=l"(r2), "=l"(r3) : "l"(p));
    F8 o;
    o.v[0] = __uint_as_float((unsigned)(r0));       o.v[1] = __uint_as_float((unsigned)(r0 >> 32));
    o.v[2] = __uint_as_float((unsigned)(r1));       o.v[3] = __uint_as_float((unsigned)(r1 >> 32));
    o.v[4] = __uint_as_float((unsigned)(r2));       o.v[5] = __uint_as_float((unsigned)(r2 >> 32));
    o.v[6] = __uint_as_float((unsigned)(r3));       o.v[7] = __uint_as_float((unsigned)(r3 >> 32));
    return o;
}

__device__ __forceinline__ void stg_sticky8(float* p, const F8& s) {
    unsigned long long r0 = (unsigned long long)__float_as_uint(s.v[0]) | ((unsigned long long)__float_as_uint(s.v[1]) << 32);
    unsigned long long r1 = (unsigned long long)__float_as_uint(s.v[2]) | ((unsigned long long)__float_as_uint(s.v[3]) << 32);
    unsigned long long r2 = (unsigned long long)__float_as_uint(s.v[4]) | ((unsigned long long)__float_as_uint(s.v[5]) << 32);
    unsigned long long r3 = (unsigned long long)__float_as_uint(s.v[6]) | ((unsigned long long)__float_as_uint(s.v[7]) << 32);
    asm volatile("st.global.L2::evict_last.v4.b64 [%0], {%1,%2,%3,%4};"
                 :: "l"(p), "l"(r0), "l"(r1), "l"(r2), "l"(r3) : "memory");
}

__device__ __forceinline__ void lif_step8(F8& mem, const F8& xt, F8& s) {
    #pragma unroll
    for (int k = 0; k < 8; k++) {
        float m = TAU * mem.v[k] + xt.v[k];
        s.v[k]   = (m > V_TH) ? 1.0f : 0.0f;
        mem.v[k] = (m > V_TH) ? 0.0f : m;
    }
}

__global__ __launch_bounds__(256) void lif_kernel(
    const float* __restrict__ x,
    const float* __restrict__ mem0,
    float* __restrict__ out,
    int n8)          // 32-byte chunks per timestep: B*C*H*W/8 = 1,048,576
{
    int i = blockIdx.x * blockDim.x + threadIdx.x;
    if (i >= n8) return;

    // CHW/8 = 128*32*32/8 = 16384 = 2^14 -> mask for B-broadcast of mem0
    const int CHW8_MASK = 16383;

    F8 mem;
    {
        const float4* m4 = (const float4*)(mem0) + 2 * (size_t)(i & CHW8_MASK);
        float4 a = __ldg(m4), b = __ldg(m4 + 1);
        mem.v[0] = a.x; mem.v[1] = a.y; mem.v[2] = a.z; mem.v[3] = a.w;
        mem.v[4] = b.x; mem.v[5] = b.y; mem.v[6] = b.z; mem.v[7] = b.w;
    }

    // Front-batch 4 streaming 32B loads: 128 B in flight per thread.
    F8 x0 = ldg_stream8(x + 8 * ((size_t)0 * n8 + i));
    F8 x1 = ldg_stream8(x + 8 * ((size_t)1 * n8 + i));
    F8 x2 = ldg_stream8(x + 8 * ((size_t)2 * n8 + i));
    F8 x3 = ldg_stream8(x + 8 * ((size_t)3 * n8 + i));

    F8 s;
    lif_step8(mem, x0, s); stg_sticky8(out + 8 * ((size_t)0 * n8 + i), s);
    lif_step8(mem, x1, s); stg_sticky8(out + 8 * ((size_t)1 * n8 + i), s);
    lif_step8(mem, x2, s); stg_sticky8(out + 8 * ((size_t)2 * n8 + i), s);
    lif_step8(mem, x3, s); stg_sticky8(out + 8 * ((size_t)3 * n8 + i), s);
}

extern "C" void kernel_launch(void* const* d_in, const int* in_sizes, int n_in,
                              void* d_out, int out_size) {
    const float* x    = (const float*)d_in[0];   // [4, 64, 128, 32, 32]
    const float* mem0 = (const float*)d_in[1];   // [1, 128, 32, 32]
    float* out = (float*)d_out;

    int n_per_t = in_sizes[0] / 4;       // 8,388,608 elems per timestep
    int n8 = n_per_t / 8;                // 1,048,576 32-byte chunks

    int threads = 256;
    int blocks = (n8 + threads - 1) / threads;   // 4096
    lif_kernel<<<blocks, threads>>>(x, mem0, out, n8);
}

// round 10
// speedup vs baseline: 1.0028x; 1.0028x over previous
#include <cuda_runtime.h>
#include <cuda_bf16.h>

// LIF recurrence over T=4 steps.
// x: [T=4, B=64, C=128, H=32, W=32] fp32; mem0: [1, C, H, W] fp32 (B-broadcast)
// out: [T, B, C, H, W] fp32 in {0,1}
// Per element: mem = tau*mem + x[t]; s = (mem > v_th); mem = s ? 0 : mem.
//
// HBM-bound. 256-bit accesses (LDG.256/STG.256), BOTH streams evict_first:
// no sticky L2 state carried between graph replays (evict_last regressed the
// replay loop in R9 by forcing writebacks onto the read path).
// 1 x 32B chunk/thread/timestep, 256-thread blocks.

#define TAU 0.25f
#define V_TH 1.0f

struct F8 { float v[8]; };

__device__ __forceinline__ F8 ldg_stream8(const float* p) {
    unsigned long long r0, r1, r2, r3;
    asm volatile("ld.global.nc.L2::evict_first.v4.b64 {%0,%1,%2,%3}, [%4];"
                 : "=l"(r0), "=l"(r1), "=l"(r2), "=l"(r3) : "l"(p));
    F8 o;
    o.v[0] = __uint_as_float((unsigned)(r0));       o.v[1] = __uint_as_float((unsigned)(r0 >> 32));
    o.v[2] = __uint_as_float((unsigned)(r1));       o.v[3] = __uint_as_float((unsigned)(r1 >> 32));
    o.v[4] = __uint_as_float((unsigned)(r2));       o.v[5] = __uint_as_float((unsigned)(r2 >> 32));
    o.v[6] = __uint_as_float((unsigned)(r3));       o.v[7] = __uint_as_float((unsigned)(r3 >> 32));
    return o;
}

__device__ __forceinline__ void stg_stream8(float* p, const F8& s) {
    unsigned long long r0 = (unsigned long long)__float_as_uint(s.v[0]) | ((unsigned long long)__float_as_uint(s.v[1]) << 32);
    unsigned long long r1 = (unsigned long long)__float_as_uint(s.v[2]) | ((unsigned long long)__float_as_uint(s.v[3]) << 32);
    unsigned long long r2 = (unsigned long long)__float_as_uint(s.v[4]) | ((unsigned long long)__float_as_uint(s.v[5]) << 32);
    unsigned long long r3 = (unsigned long long)__float_as_uint(s.v[6]) | ((unsigned long long)__float_as_uint(s.v[7]) << 32);
    asm volatile("st.global.L2::evict_first.v4.b64 [%0], {%1,%2,%3,%4};"
                 :: "l"(p), "l"(r0), "l"(r1), "l"(r2), "l"(r3) : "memory");
}

__device__ __forceinline__ void lif_step8(F8& mem, const F8& xt, F8& s) {
    #pragma unroll
    for (int k = 0; k < 8; k++) {
        float m = TAU * mem.v[k] + xt.v[k];
        s.v[k]   = (m > V_TH) ? 1.0f : 0.0f;
        mem.v[k] = (m > V_TH) ? 0.0f : m;
    }
}

__global__ __launch_bounds__(256) void lif_kernel(
    const float* __restrict__ x,
    const float* __restrict__ mem0,
    float* __restrict__ out,
    int n8)          // 32-byte chunks per timestep: B*C*H*W/8 = 1,048,576
{
    int i = blockIdx.x * blockDim.x + threadIdx.x;
    if (i >= n8) return;

    // CHW/8 = 128*32*32/8 = 16384 = 2^14 -> mask for B-broadcast of mem0
    const int CHW8_MASK = 16383;

    F8 mem;
    {
        const float4* m4 = (const float4*)(mem0) + 2 * (size_t)(i & CHW8_MASK);
        float4 a = __ldg(m4), b = __ldg(m4 + 1);
        mem.v[0] = a.x; mem.v[1] = a.y; mem.v[2] = a.z; mem.v[3] = a.w;
        mem.v[4] = b.x; mem.v[5] = b.y; mem.v[6] = b.z; mem.v[7] = b.w;
    }

    // Front-batch 4 streaming 32B loads: 128 B in flight per thread.
    F8 x0 = ldg_stream8(x + 8 * ((size_t)0 * n8 + i));
    F8 x1 = ldg_stream8(x + 8 * ((size_t)1 * n8 + i));
    F8 x2 = ldg_stream8(x + 8 * ((size_t)2 * n8 + i));
    F8 x3 = ldg_stream8(x + 8 * ((size_t)3 * n8 + i));

    F8 s;
    lif_step8(mem, x0, s); stg_stream8(out + 8 * ((size_t)0 * n8 + i), s);
    lif_step8(mem, x1, s); stg_stream8(out + 8 * ((size_t)1 * n8 + i), s);
    lif_step8(mem, x2, s); stg_stream8(out + 8 * ((size_t)2 * n8 + i), s);
    lif_step8(mem, x3, s); stg_stream8(out + 8 * ((size_t)3 * n8 + i), s);
}

extern "C" void kernel_launch(void* const* d_in, const int* in_sizes, int n_in,
                              void* d_out, int out_size) {
    const float* x    = (const float*)d_in[0];   // [4, 64, 128, 32, 32]
    const float* mem0 = (const float*)d_in[1];   // [1, 128, 32, 32]
    float* out = (float*)d_out;

    int n_per_t = in_sizes[0] / 4;       // 8,388,608 elems per timestep
    int n8 = n_per_t / 8;                // 1,048,576 32-byte chunks

    int threads = 256;
    int blocks = (n8 + threads - 1) / threads;   // 4096
    lif_kernel<<<blocks, threads>>>(x, mem0, out, n8);
}

// round 11
// speedup vs baseline: 1.0397x; 1.0368x over previous
#include <cuda_runtime.h>
#include <cuda_bf16.h>

// LIF recurrence over T=4 steps. FINAL — empirically best config (R6/R7).
// x: [T=4, B=64, C=128, H=32, W=32] fp32; mem0: [1, C, H, W] fp32 (B-broadcast)
// out: [T, B, C, H, W] fp32 in {0,1}
// Per element: mem = tau*mem + x[t]; s = (mem > v_th); mem = s ? 0 : mem.
//
// HBM-bound at the mixed R/W stream floor (~7.4 TB/s effective, 268 MB
// compulsory traffic). Ten configurations tested; kernel time pinned at
// 36.1-37.5us regardless of occupancy (52-90%), MLP (4-8), vector width
// (128/256-bit), L2 eviction policy, or grid shape. This config:
// 1 float4/thread, 256-thread blocks, 4 front-batched evict-first LDG.128,
// evict-first STG.128, 32 regs, one-shot grid.

#define TAU 0.25f
#define V_TH 1.0f

__device__ __forceinline__ void lif_step(float4& mem, const float4& xt, float4& s) {
    mem.x = TAU * mem.x + xt.x; s.x = (mem.x > V_TH) ? 1.0f : 0.0f; mem.x = (mem.x > V_TH) ? 0.0f : mem.x;
    mem.y = TAU * mem.y + xt.y; s.y = (mem.y > V_TH) ? 1.0f : 0.0f; mem.y = (mem.y > V_TH) ? 0.0f : mem.y;
    mem.z = TAU * mem.z + xt.z; s.z = (mem.z > V_TH) ? 1.0f : 0.0f; mem.z = (mem.z > V_TH) ? 0.0f : mem.z;
    mem.w = TAU * mem.w + xt.w; s.w = (mem.w > V_TH) ? 1.0f : 0.0f; mem.w = (mem.w > V_TH) ? 0.0f : mem.w;
}

__global__ __launch_bounds__(256) void lif_kernel(
    const float4* __restrict__ x,
    const float4* __restrict__ mem0,
    float4* __restrict__ out,
    int n4)          // float4 units per timestep: B*C*H*W/4 = 2,097,152
{
    int i = blockIdx.x * blockDim.x + threadIdx.x;
    if (i >= n4) return;

    // CHW/4 = 128*32*32/4 = 32768 = 2^15 -> mask for B-broadcast of mem0
    const int CHW4_MASK = 32767;
    float4 mem = __ldg(&mem0[i & CHW4_MASK]);

    // Front-batch the 4 streaming loads (evict-first), 64 B in flight/thread.
    float4 x0 = __ldcs(&x[0 * (size_t)n4 + i]);
    float4 x1 = __ldcs(&x[1 * (size_t)n4 + i]);
    float4 x2 = __ldcs(&x[2 * (size_t)n4 + i]);
    float4 x3 = __ldcs(&x[3 * (size_t)n4 + i]);

    float4 s;
    lif_step(mem, x0, s); __stcs(&out[0 * (size_t)n4 + i], s);
    lif_step(mem, x1, s); __stcs(&out[1 * (size_t)n4 + i], s);
    lif_step(mem, x2, s); __stcs(&out[2 * (size_t)n4 + i], s);
    lif_step(mem, x3, s); __stcs(&out[3 * (size_t)n4 + i], s);
}

extern "C" void kernel_launch(void* const* d_in, const int* in_sizes, int n_in,
                              void* d_out, int out_size) {
    const float4* x    = (const float4*)d_in[0];   // [4, 64, 128, 32, 32]
    const float4* mem0 = (const float4*)d_in[1];   // [1, 128, 32, 32]
    float4* out = (float4*)d_out;

    int n_per_t = in_sizes[0] / 4;       // 8,388,608 elems per timestep
    int n4 = n_per_t / 4;                // 2,097,152 float4 units

    int threads = 256;
    int blocks = (n4 + threads - 1) / threads;   // 8192
    lif_kernel<<<blocks, threads>>>(x, mem0, out, n4);
}